// round 3
// baseline (speedup 1.0000x reference)
#include <cuda_runtime.h>
#include <cstdint>

#define N_NODES 50000
#define CH 64

// scratch accumulator — float4 type guarantees 16B alignment
__device__ float4 g_agg4[N_NODES * (CH / 4)];
// dtype flag for edge_index: 1 = int64, 0 = int32
__device__ int g_ei_is64;

// ---------------------------------------------------------------------------
// Kernel 0: detect edge_index dtype. If data is int64 with values < 2^31,
// every odd 32-bit word is zero. Random int32 indices make that impossible.
// ---------------------------------------------------------------------------
__global__ void detect_kernel(const int* __restrict__ ei32) {
    int is64 = 1;
    #pragma unroll
    for (int k = 0; k < 64; k++) {
        if (ei32[2 * k + 1] != 0) { is64 = 0; break; }
    }
    g_ei_is64 = is64;
}

// ---------------------------------------------------------------------------
// Kernel 1: agg = x   (float4 copy)
// ---------------------------------------------------------------------------
__global__ void init_agg_kernel(const float4* __restrict__ x4, int n4) {
    int i = blockIdx.x * blockDim.x + threadIdx.x;
    if (i < n4) g_agg4[i] = x4[i];
}

// ---------------------------------------------------------------------------
// Kernel 2: scatter-add. One 16-lane group per edge; lane owns one float4.
// ---------------------------------------------------------------------------
__global__ void scatter_kernel(const float4* __restrict__ x4,
                               const void* __restrict__ ei_raw,
                               int nE) {
    int g = blockIdx.x * blockDim.x + threadIdx.x;
    int lane = g & 15;
    int edge = g >> 4;
    if (edge >= nE) return;

    long long src, dst;
    if (g_ei_is64) {
        const long long* ei = (const long long*)ei_raw;
        src = ei[edge];
        dst = ei[nE + edge];
    } else {
        const int* ei = (const int*)ei_raw;
        src = ei[edge];
        dst = ei[nE + edge];
    }
    // defensive: malformed index -> skip (turns crash into diagnosable rel_err)
    if ((unsigned long long)src >= N_NODES || (unsigned long long)dst >= N_NODES)
        return;

    float4 v = x4[src * 16 + lane];
    float4* dptr = g_agg4 + dst * 16 + lane;
    asm volatile("red.global.add.v4.f32 [%0], {%1, %2, %3, %4};"
                 :: "l"(dptr), "f"(v.x), "f"(v.y), "f"(v.z), "f"(v.w)
                 : "memory");
}

// ---------------------------------------------------------------------------
// Kernel 3: out = relu(h @ W^T + b), h = g_agg (already x + sum).
// ---------------------------------------------------------------------------
#define ROWS_PER_BLK 32

__global__ void __launch_bounds__(256, 4) gemm_relu_kernel(
    const float* __restrict__ W,   // [64,64] row-major (o,i)
    const float* __restrict__ b,   // [64]
    float* __restrict__ out)       // [N,64]
{
    __shared__ float sWT[64][72];
    __shared__ float sH[ROWS_PER_BLK][68];

    int t = threadIdx.x;
    int r0 = blockIdx.x * ROWS_PER_BLK;

    // load W transposed: 4096 elems / 256 threads = 16 each
    #pragma unroll
    for (int k = 0; k < 16; k++) {
        int idx = t + k * 256;       // idx = o*64 + i
        int o = idx >> 6;
        int i = idx & 63;
        sWT[i][o] = W[idx];
    }
    // load h tile: 32 rows x 64 = 512 float4, 2 per thread
    #pragma unroll
    for (int k = 0; k < 2; k++) {
        int idx = t + k * 256;
        int r = idx >> 4;
        int c = idx & 15;
        int row = r0 + r;
        float4 v = (row < N_NODES) ? g_agg4[row * 16 + c]
                                   : make_float4(0.f, 0.f, 0.f, 0.f);
        sH[r][c * 4 + 0] = v.x;
        sH[r][c * 4 + 1] = v.y;
        sH[r][c * 4 + 2] = v.z;
        sH[r][c * 4 + 3] = v.w;
    }
    __syncthreads();

    int r = t >> 3;          // local row 0..31
    int o0 = (t & 7) * 8;    // output group

    float acc[8];
    #pragma unroll
    for (int k = 0; k < 8; k++) acc[k] = b[o0 + k];

    #pragma unroll
    for (int i = 0; i < 64; i++) {
        float hv = sH[r][i];
        #pragma unroll
        for (int k = 0; k < 8; k++)
            acc[k] += hv * sWT[i][o0 + k];
    }

    int row = r0 + r;
    if (row < N_NODES) {
        float4 v0, v1;
        v0.x = fmaxf(acc[0], 0.f); v0.y = fmaxf(acc[1], 0.f);
        v0.z = fmaxf(acc[2], 0.f); v0.w = fmaxf(acc[3], 0.f);
        v1.x = fmaxf(acc[4], 0.f); v1.y = fmaxf(acc[5], 0.f);
        v1.z = fmaxf(acc[6], 0.f); v1.w = fmaxf(acc[7], 0.f);
        float4* o4 = reinterpret_cast<float4*>(out + row * CH + o0);
        o4[0] = v0;
        o4[1] = v1;
    }
}

// ---------------------------------------------------------------------------
extern "C" void kernel_launch(void* const* d_in, const int* in_sizes, int n_in,
                              void* d_out, int out_size) {
    const float* x  = (const float*)d_in[0];
    const void*  ei = d_in[1];
    const float* W  = (const float*)d_in[2];
    const float* b  = (const float*)d_in[3];
    float* out = (float*)d_out;

    int nE = in_sizes[1] / 2;                 // 800000
    int n4 = (N_NODES * CH) / 4;              // 800000 float4

    detect_kernel<<<1, 1>>>((const int*)ei);

    init_agg_kernel<<<(n4 + 255) / 256, 256>>>(
        reinterpret_cast<const float4*>(x), n4);

    long long threads = (long long)nE * 16;
    int blocks = (int)((threads + 255) / 256);
    scatter_kernel<<<blocks, 256>>>(
        reinterpret_cast<const float4*>(x), ei, nE);

    int gblocks = (N_NODES + ROWS_PER_BLK - 1) / ROWS_PER_BLK;
    gemm_relu_kernel<<<gblocks, 256>>>(W, b, out);
}

// round 5
// speedup vs baseline: 1.5953x; 1.5953x over previous
#include <cuda_runtime.h>
#include <cstdint>

#define N_NODES 50000
#define CH 64

// scratch accumulator — float4 type guarantees 16B alignment
__device__ float4 g_agg4[N_NODES * (CH / 4)];
// dtype flag for edge_index: 1 = int64, 0 = int32
__device__ int g_ei_is64;

// ---------------------------------------------------------------------------
// Kernel 1: agg = x (float4 copy) + fold in edge-index dtype detection.
// ---------------------------------------------------------------------------
__global__ void init_agg_kernel(const float4* __restrict__ x4, int n4,
                                const int* __restrict__ ei32) {
    int i = blockIdx.x * blockDim.x + threadIdx.x;
    if (i < n4) g_agg4[i] = x4[i];
    if (blockIdx.x == 0 && threadIdx.x == 0) {
        int is64 = 1;
        #pragma unroll
        for (int k = 0; k < 64; k++) {
            if (ei32[2 * k + 1] != 0) { is64 = 0; break; }
        }
        g_ei_is64 = is64;
    }
}

// ---------------------------------------------------------------------------
// Kernel 2: scatter-add. One 16-lane group per edge; lane owns one float4.
// ---------------------------------------------------------------------------
__global__ void scatter_kernel(const float4* __restrict__ x4,
                               const void* __restrict__ ei_raw,
                               int nE) {
    int g = blockIdx.x * blockDim.x + threadIdx.x;
    int lane = g & 15;
    int edge = g >> 4;
    if (edge >= nE) return;

    long long src, dst;
    if (g_ei_is64) {
        const long long* ei = (const long long*)ei_raw;
        src = ei[edge];
        dst = ei[nE + edge];
    } else {
        const int* ei = (const int*)ei_raw;
        src = ei[edge];
        dst = ei[nE + edge];
    }
    if ((unsigned long long)src >= N_NODES || (unsigned long long)dst >= N_NODES)
        return;

    float4 v = x4[src * 16 + lane];
    float4* dptr = g_agg4 + dst * 16 + lane;
    asm volatile("red.global.add.v4.f32 [%0], {%1, %2, %3, %4};"
                 :: "l"(dptr), "f"(v.x), "f"(v.y), "f"(v.z), "f"(v.w)
                 : "memory");
}

// ---------------------------------------------------------------------------
// Kernel 3: out = relu(h @ W^T + b), h = g_agg.
// 128 rows/block, 128 threads, dynamic smem. Thread (tr=t>>3, tc=t&7)
// computes an 8x8 output tile. sHT is k-major so 8 consecutive rows = 2x
// LDS.128 (broadcast within 8-lane groups). Per k-step: 4 LDS.128 -> 64 FFMA.
// ---------------------------------------------------------------------------
#define GROWS 128
#define GTHREADS 128
#define HT_STRIDE (GROWS + 8)   // floats; keeps float4 alignment (8 | stride offsets)
#define WT_STRIDE 72
#define SMEM_BYTES ((64 * HT_STRIDE + 64 * WT_STRIDE) * 4)

__global__ void __launch_bounds__(GTHREADS) gemm_relu_kernel(
    const float* __restrict__ W,   // [64,64] row-major (o,i)
    const float* __restrict__ b,   // [64]
    float* __restrict__ out)       // [N,64]
{
    extern __shared__ float smem[];
    float* sHT = smem;                       // [64][HT_STRIDE]  (k-major)
    float* sWT = smem + 64 * HT_STRIDE;      // [64][WT_STRIDE]  (k-major)

    int t = threadIdx.x;
    int r0 = blockIdx.x * GROWS;

    // Stage W transposed: 4096 / 128 threads = 32 each
    #pragma unroll
    for (int k = 0; k < 32; k++) {
        int idx = t + k * 128;       // idx = o*64 + i
        int o = idx >> 6;
        int i = idx & 63;
        sWT[i * WT_STRIDE + o] = W[idx];
    }
    // Stage h transposed: thread t owns global row r0+t
    {
        int row = r0 + t;
        if (row < N_NODES) {
            #pragma unroll
            for (int j = 0; j < 16; j++) {
                float4 v = g_agg4[row * 16 + j];
                sHT[(j * 4 + 0) * HT_STRIDE + t] = v.x;
                sHT[(j * 4 + 1) * HT_STRIDE + t] = v.y;
                sHT[(j * 4 + 2) * HT_STRIDE + t] = v.z;
                sHT[(j * 4 + 3) * HT_STRIDE + t] = v.w;
            }
        } else {
            #pragma unroll
            for (int i = 0; i < 64; i++) sHT[i * HT_STRIDE + t] = 0.f;
        }
    }
    __syncthreads();

    int tr = t >> 3;         // 0..15 -> row group
    int tc = t & 7;          // 0..7  -> col group
    int rbase = tr * 8;
    int obase = tc * 8;

    float acc[8][8];
    #pragma unroll
    for (int r = 0; r < 8; r++)
        #pragma unroll
        for (int c = 0; c < 8; c++)
            acc[r][c] = b[obase + c];

    #pragma unroll 8
    for (int i = 0; i < 64; i++) {
        float4 h0 = *reinterpret_cast<const float4*>(&sHT[i * HT_STRIDE + rbase]);
        float4 h1 = *reinterpret_cast<const float4*>(&sHT[i * HT_STRIDE + rbase + 4]);
        float4 w0 = *reinterpret_cast<const float4*>(&sWT[i * WT_STRIDE + obase]);
        float4 w1 = *reinterpret_cast<const float4*>(&sWT[i * WT_STRIDE + obase + 4]);
        float hv[8] = {h0.x, h0.y, h0.z, h0.w, h1.x, h1.y, h1.z, h1.w};
        float wv[8] = {w0.x, w0.y, w0.z, w0.w, w1.x, w1.y, w1.z, w1.w};
        #pragma unroll
        for (int r = 0; r < 8; r++)
            #pragma unroll
            for (int c = 0; c < 8; c++)
                acc[r][c] += hv[r] * wv[c];
    }

    #pragma unroll
    for (int r = 0; r < 8; r++) {
        int row = r0 + rbase + r;
        if (row < N_NODES) {
            float4 v0, v1;
            v0.x = fmaxf(acc[r][0], 0.f); v0.y = fmaxf(acc[r][1], 0.f);
            v0.z = fmaxf(acc[r][2], 0.f); v0.w = fmaxf(acc[r][3], 0.f);
            v1.x = fmaxf(acc[r][4], 0.f); v1.y = fmaxf(acc[r][5], 0.f);
            v1.z = fmaxf(acc[r][6], 0.f); v1.w = fmaxf(acc[r][7], 0.f);
            float4* o4 = reinterpret_cast<float4*>(out + row * CH + obase);
            o4[0] = v0;
            o4[1] = v1;
        }
    }
}

// ---------------------------------------------------------------------------
extern "C" void kernel_launch(void* const* d_in, const int* in_sizes, int n_in,
                              void* d_out, int out_size) {
    const float* x  = (const float*)d_in[0];
    const void*  ei = d_in[1];
    const float* W  = (const float*)d_in[2];
    const float* b  = (const float*)d_in[3];
    float* out = (float*)d_out;

    int nE = in_sizes[1] / 2;                 // 800000
    int n4 = (N_NODES * CH) / 4;              // 800000 float4

    static bool attr_done = false;
    if (!attr_done) {
        cudaFuncSetAttribute(gemm_relu_kernel,
                             cudaFuncAttributeMaxDynamicSharedMemorySize,
                             SMEM_BYTES);
        attr_done = true;
    }

    init_agg_kernel<<<(n4 + 255) / 256, 256>>>(
        reinterpret_cast<const float4*>(x), n4, (const int*)ei);

    long long threads = (long long)nE * 16;
    int blocks = (int)((threads + 255) / 256);
    scatter_kernel<<<blocks, 256>>>(
        reinterpret_cast<const float4*>(x), ei, nE);

    int gblocks = (N_NODES + GROWS - 1) / GROWS;
    gemm_relu_kernel<<<gblocks, GTHREADS, SMEM_BYTES>>>(W, b, out);
}